// round 1
// baseline (speedup 1.0000x reference)
#include <cuda_runtime.h>
#include <cuda_bf16.h>
#include <cstdint>

#define S_DIM 1024
#define B_DIM 32
#define D_DIM 1024
#define E_DIM 1024
#define M_TOTAL (S_DIM*B_DIM)

// ---------------- device scratch (static, no allocations) ----------------
__device__ __nv_bfloat16 g_wv_bf[E_DIM*D_DIM];   // Wv in bf16, [E][D] k-major
__device__ float g_pq[B_DIM*E_DIM];              // projected query [B][E]
__device__ float g_scale_v[E_DIM];               // g/||v|| * v
__device__ float g_scores[M_TOTAL];              // raw scores, then attn [S][B]

__device__ __forceinline__ float fast_tanh(float x){
    float y; asm("tanh.approx.f32 %0, %1;" : "=f"(y) : "f"(x)); return y;
}
__device__ __forceinline__ uint32_t smem_u32(const void* p){
    return (uint32_t)__cvta_generic_to_shared(p);
}

// ---------------- kernel 1: scale_v = g/||v|| * v ----------------
__global__ void scale_v_kernel(const float* __restrict__ v, const float* __restrict__ g){
    __shared__ float red[32];
    int t = threadIdx.x;              // 1024 threads
    float x = v[t];
    float s = x*x;
    #pragma unroll
    for (int o=16;o;o>>=1) s += __shfl_xor_sync(0xffffffffu, s, o);
    if ((t&31)==0) red[t>>5] = s;
    __syncthreads();
    if (t < 32){
        float z = red[t];
        #pragma unroll
        for (int o=16;o;o>>=1) z += __shfl_xor_sync(0xffffffffu, z, o);
        if (t==0) red[0] = z;
    }
    __syncthreads();
    float scale = g[0] / sqrtf(red[0]);
    g_scale_v[t] = scale * x;
}

// ---------------- kernel 2: Wv fp32 -> bf16 ----------------
__global__ void wv_convert_kernel(const float* __restrict__ Wv){
    int i = blockIdx.x*256 + threadIdx.x;       // grid = 1024 -> covers 1M elems as float4
    float4 f = reinterpret_cast<const float4*>(Wv)[i];
    __nv_bfloat162* dst = reinterpret_cast<__nv_bfloat162*>(g_wv_bf) + 2*(size_t)i;
    dst[0] = __floats2bfloat162_rn(f.x, f.y);
    dst[1] = __floats2bfloat162_rn(f.z, f.w);
}

// ---------------- kernel 3: pq[b][e] = query[b]·Wq[e] + bq[e] ----------------
__global__ void pq_kernel(const float* __restrict__ query, const float* __restrict__ Wq,
                          const float* __restrict__ bq){
    int o = blockIdx.x*8 + (threadIdx.x>>5);    // global warp id = b*1024+e
    int lane = threadIdx.x & 31;
    int b = o >> 10, e = o & 1023;
    const float4* q = reinterpret_cast<const float4*>(query) + (size_t)b*256;
    const float4* w = reinterpret_cast<const float4*>(Wq) + (size_t)e*256;
    float s = 0.f;
    for (int k = lane; k < 256; k += 32){
        float4 qa = q[k], wa = w[k];
        s += qa.x*wa.x + qa.y*wa.y + qa.z*wa.z + qa.w*wa.w;
    }
    #pragma unroll
    for (int o2=16;o2;o2>>=1) s += __shfl_xor_sync(0xffffffffu, s, o2);
    if (lane==0) g_pq[o] = s + bq[e];
}

// ---------------- kernel 4: fused K-GEMM + tanh + scale_v reduce ----------------
// scores[m] = sum_e tanh(pq[m%32][e] + sum_d value[m][d]*Wv[e][d]) * scale_v[e]
#define BM 64
#define A_STRIDE 1032     // bf16 elems per padded row (2064 B, 16B aligned, +4 bank shift)
#define BV_STRIDE 72      // bf16 elems per padded Wv row (144 B)
#define OFF_A 0
#define SZ_A (BM*A_STRIDE*2)           // 132096
#define OFF_B (OFF_A + SZ_A)
#define SZ_B (2*64*BV_STRIDE*2)        // 18432
#define OFF_PQ (OFF_B + SZ_B)
#define SZ_PQ (32*64*4)                // 8192
#define OFF_SV (OFF_PQ + SZ_PQ)
#define SZ_SV (64*4)
#define OFF_SC (OFF_SV + SZ_SV)
#define SZ_SC (2*64*4)
#define SMEM_TOTAL (OFF_SC + SZ_SC)    // 159488 bytes

__device__ __forceinline__ void load_b_chunk(__nv_bfloat16* sB, int buf, int nc, int kc, int tid){
    const __nv_bfloat16* src_base = g_wv_bf + (size_t)(nc*64)*D_DIM + kc*64;
    __nv_bfloat16* dst_base = sB + buf*64*BV_STRIDE;
    #pragma unroll
    for (int i = 0; i < 2; i++){
        int idx = tid + i*256;
        int r = idx >> 3, c = idx & 7;
        uint32_t dst = smem_u32(dst_base + r*BV_STRIDE + c*8);
        const void* src = src_base + (size_t)r*D_DIM + c*8;
        asm volatile("cp.async.cg.shared.global [%0], [%1], 16;\n" :: "r"(dst), "l"(src));
    }
}

__global__ void __launch_bounds__(256,1) score_kernel(const float* __restrict__ value){
    extern __shared__ char smem[];
    __nv_bfloat16* sA = (__nv_bfloat16*)(smem + OFF_A);
    __nv_bfloat16* sB = (__nv_bfloat16*)(smem + OFF_B);
    float* sPQ = (float*)(smem + OFF_PQ);
    float* sSV = (float*)(smem + OFF_SV);
    float* sSC = (float*)(smem + OFF_SC);

    int tid = threadIdx.x, lane = tid & 31, warp = tid >> 5;
    int m0 = blockIdx.x * BM;

    // Load resident A tile: value rows m0..m0+63, fp32 -> bf16 (converted inline)
    for (int i = tid; i < BM*256; i += 256){
        int r = i >> 8, c4 = i & 255;
        float4 f = reinterpret_cast<const float4*>(value)[(size_t)(m0+r)*256 + c4];
        __nv_bfloat162* d = reinterpret_cast<__nv_bfloat162*>(sA + r*A_STRIDE + c4*4);
        d[0] = __floats2bfloat162_rn(f.x, f.y);
        d[1] = __floats2bfloat162_rn(f.z, f.w);
    }

    int wm = (warp >> 1) * 16;          // warp row base (local)
    int wn = (warp & 1) * 32;           // warp col base within n-chunk
    int g  = lane >> 2, t2 = (lane & 3) * 2;

    float rs0 = 0.f, rs1 = 0.f;         // per-lane running score for rows g, g+8
    int b0i = (m0 + wm + g) & 31;
    int b1i = (m0 + wm + g + 8) & 31;

    for (int nc = 0; nc < 16; nc++){
        __syncthreads();   // protects sPQ/sSV overwrite vs previous epilogue + A tile on nc=0
        // load pq tile [32][64] and scale_v chunk for these 64 E-columns
        {
            int base = nc*64;
            for (int i = tid; i < 32*64; i += 256){
                int bb = i >> 6, cc = i & 63;
                sPQ[i] = g_pq[bb*E_DIM + base + cc];
            }
            if (tid < 64) sSV[tid] = g_scale_v[base + tid];
        }

        float acc[4][4];
        #pragma unroll
        for (int i=0;i<4;i++)
            #pragma unroll
            for (int j=0;j<4;j++) acc[i][j]=0.f;

        load_b_chunk(sB, 0, nc, 0, tid);
        asm volatile("cp.async.commit_group;\n");

        for (int kc = 0; kc < 16; kc++){
            if (kc + 1 < 16){
                load_b_chunk(sB, (kc+1)&1, nc, kc+1, tid);
                asm volatile("cp.async.commit_group;\n");
                asm volatile("cp.async.wait_group 1;\n");
            } else {
                asm volatile("cp.async.wait_group 0;\n");
            }
            __syncthreads();
            const __nv_bfloat16* bb = sB + (kc&1)*64*BV_STRIDE;
            #pragma unroll
            for (int ks = 0; ks < 4; ks++){
                int kk = kc*64 + ks*16;
                uint32_t a0 = *(const uint32_t*)(sA + (wm+g  )*A_STRIDE + kk + t2);
                uint32_t a1 = *(const uint32_t*)(sA + (wm+g+8)*A_STRIDE + kk + t2);
                uint32_t a2 = *(const uint32_t*)(sA + (wm+g  )*A_STRIDE + kk + t2 + 8);
                uint32_t a3 = *(const uint32_t*)(sA + (wm+g+8)*A_STRIDE + kk + t2 + 8);
                int kl = ks*16;
                #pragma unroll
                for (int ns = 0; ns < 4; ns++){
                    const __nv_bfloat16* brow = bb + (wn + ns*8 + g)*BV_STRIDE + kl;
                    uint32_t b0 = *(const uint32_t*)(brow + t2);
                    uint32_t b1 = *(const uint32_t*)(brow + t2 + 8);
                    asm volatile(
                        "mma.sync.aligned.m16n8k16.row.col.f32.bf16.bf16.f32 "
                        "{%0,%1,%2,%3}, {%4,%5,%6,%7}, {%8,%9}, {%0,%1,%2,%3};\n"
                        : "+f"(acc[ns][0]), "+f"(acc[ns][1]), "+f"(acc[ns][2]), "+f"(acc[ns][3])
                        : "r"(a0), "r"(a1), "r"(a2), "r"(a3), "r"(b0), "r"(b1));
                }
            }
            __syncthreads();
        }

        // epilogue: tanh(pq + acc) * scale_v, reduce over these 64 columns
        #pragma unroll
        for (int ns = 0; ns < 4; ns++){
            int cl = wn + ns*8 + t2;
            float sv0 = sSV[cl], sv1 = sSV[cl+1];
            rs0 += fast_tanh(acc[ns][0] + sPQ[b0i*64 + cl    ]) * sv0
                 + fast_tanh(acc[ns][1] + sPQ[b0i*64 + cl + 1]) * sv1;
            rs1 += fast_tanh(acc[ns][2] + sPQ[b1i*64 + cl    ]) * sv0
                 + fast_tanh(acc[ns][3] + sPQ[b1i*64 + cl + 1]) * sv1;
        }
    }

    // reduce rs across the lane quad (lanes sharing a row)
    rs0 += __shfl_xor_sync(0xffffffffu, rs0, 1);
    rs0 += __shfl_xor_sync(0xffffffffu, rs0, 2);
    rs1 += __shfl_xor_sync(0xffffffffu, rs1, 1);
    rs1 += __shfl_xor_sync(0xffffffffu, rs1, 2);
    if ((lane & 3) == 0){
        sSC[(warp&1)*64 + wm + g    ] = rs0;
        sSC[(warp&1)*64 + wm + 8 + g] = rs1;
    }
    __syncthreads();
    if (tid < 64) g_scores[m0 + tid] = sSC[tid] + sSC[64 + tid];
}

// ---------------- kernel 5: softmax over s per b ----------------
__global__ void softmax_kernel(const unsigned char* __restrict__ mask,
                               float* __restrict__ out1, float* __restrict__ out2){
    __shared__ float red[32];
    __shared__ float bval;
    int b = blockIdx.x, s = threadIdx.x;     // 1024 threads
    int idx = s*B_DIM + b;
    float x = g_scores[idx];
    if (mask[idx]) x = -1e30f;

    float m = x;
    #pragma unroll
    for (int o=16;o;o>>=1) m = fmaxf(m, __shfl_xor_sync(0xffffffffu, m, o));
    if ((s&31)==0) red[s>>5] = m;
    __syncthreads();
    if (s < 32){
        float z = red[s];
        #pragma unroll
        for (int o=16;o;o>>=1) z = fmaxf(z, __shfl_xor_sync(0xffffffffu, z, o));
        if (s==0) bval = z;
    }
    __syncthreads();
    float e = __expf(x - bval);
    float t = e;
    #pragma unroll
    for (int o=16;o;o>>=1) t += __shfl_xor_sync(0xffffffffu, t, o);
    if ((s&31)==0) red[s>>5] = t;
    __syncthreads();
    if (s < 32){
        float z = red[s];
        #pragma unroll
        for (int o=16;o;o>>=1) z += __shfl_xor_sync(0xffffffffu, z, o);
        if (s==0) bval = z;
    }
    __syncthreads();
    float a = e / bval;
    g_scores[idx] = a;              // reuse as attn for context kernel
    if (out1) out1[idx] = a;
    if (out2) out2[idx] = a;
}

// ---------------- kernel 6: context[b][d] = sum_s attn[s][b] * value[s][b][d] ----------------
__global__ void context_kernel(const float* __restrict__ value, float* __restrict__ ctx){
    int b = blockIdx.y;
    int d = blockIdx.x*256 + threadIdx.x;
    const float* vp = value + (size_t)b*D_DIM + d;
    float acc = 0.f;
    for (int s = 0; s < S_DIM; s += 8){
        float a[8], vv[8];
        #pragma unroll
        for (int i=0;i<8;i++){
            a[i]  = g_scores[(s+i)*B_DIM + b];
            vv[i] = vp[(size_t)(s+i)*B_DIM*D_DIM];
        }
        #pragma unroll
        for (int i=0;i<8;i++) acc += a[i]*vv[i];
    }
    ctx[(size_t)b*D_DIM + d] = acc;
}

// ---------------- launch ----------------
extern "C" void kernel_launch(void* const* d_in, const int* in_sizes, int n_in,
                              void* d_out, int out_size){
    const float* query = (const float*)d_in[0];
    const float* value = (const float*)d_in[1];
    const unsigned char* mask = (const unsigned char*)d_in[2];
    const float* Wq = (const float*)d_in[3];
    const float* bq = (const float*)d_in[4];
    const float* Wv = (const float*)d_in[5];
    const float* v  = (const float*)d_in[6];
    const float* g  = (const float*)d_in[7];
    float* out = (float*)d_out;
    (void)in_sizes; (void)n_in; (void)bq;

    cudaFuncSetAttribute(score_kernel, cudaFuncAttributeMaxDynamicSharedMemorySize, SMEM_TOTAL);

    scale_v_kernel<<<1, 1024>>>(v, g);
    wv_convert_kernel<<<1024, 256>>>(Wv);
    pq_kernel<<<4096, 256>>>(query, Wq, bq);
    score_kernel<<<M_TOTAL/BM, 256, SMEM_TOTAL>>>(value);

    float* attn1 = (out_size >= 65536) ? out + 32768 : nullptr;
    float* attn2 = (out_size >= 98304) ? out + 65536 : nullptr;
    softmax_kernel<<<32, 1024>>>(mask, attn1, attn2);
    context_kernel<<<dim3(4,32), 256>>>(value, out);
}

// round 3
// speedup vs baseline: 1.4729x; 1.4729x over previous
#include <cuda_runtime.h>
#include <cuda_bf16.h>
#include <cstdint>

#define S_DIM 1024
#define B_DIM 32
#define D_DIM 1024
#define E_DIM 1024
#define M_TOTAL (S_DIM*B_DIM)

// ---------------- device scratch (static, no allocations) ----------------
__device__ __nv_bfloat16 g_wv_bf[E_DIM*D_DIM];            // Wv bf16 [E][D] k-major
__device__ __nv_bfloat16 g_val_bf[(size_t)M_TOTAL*D_DIM]; // value bf16 [M][D]
__device__ float g_pq[B_DIM*E_DIM];                       // projected query [B][E]
__device__ float g_scale_v[E_DIM];                        // g/||v|| * v
__device__ float g_scores[M_TOTAL];                       // raw scores -> attn [S][B]

__device__ __forceinline__ float fast_tanh(float x){
    float y; asm("tanh.approx.f32 %0, %1;" : "=f"(y) : "f"(x)); return y;
}
__device__ __forceinline__ uint32_t smem_u32(const void* p){
    return (uint32_t)__cvta_generic_to_shared(p);
}
__device__ __forceinline__ void cp_async16(uint32_t dst, const void* src){
    asm volatile("cp.async.cg.shared.global [%0], [%1], 16;\n" :: "r"(dst), "l"(src));
}
__device__ __forceinline__ void ldsm_x4(uint32_t* r, uint32_t addr){
    asm volatile("ldmatrix.sync.aligned.m8n8.x4.shared.b16 {%0,%1,%2,%3}, [%4];"
                 : "=r"(r[0]), "=r"(r[1]), "=r"(r[2]), "=r"(r[3]) : "r"(addr));
}

// ---------------- kernel 1: scale_v = g/||v|| * v ----------------
__global__ void scale_v_kernel(const float* __restrict__ v, const float* __restrict__ g){
    __shared__ float red[32];
    int t = threadIdx.x;
    float x = v[t];
    float s = x*x;
    #pragma unroll
    for (int o=16;o;o>>=1) s += __shfl_xor_sync(0xffffffffu, s, o);
    if ((t&31)==0) red[t>>5] = s;
    __syncthreads();
    if (t < 32){
        float z = red[t];
        #pragma unroll
        for (int o=16;o;o>>=1) z += __shfl_xor_sync(0xffffffffu, z, o);
        if (t==0) red[0] = z;
    }
    __syncthreads();
    float scale = g[0] / sqrtf(red[0]);
    g_scale_v[t] = scale * x;
}

// ---------------- kernel 2: Wv fp32 -> bf16 ----------------
__global__ void wv_convert_kernel(const float* __restrict__ Wv){
    int i = blockIdx.x*256 + threadIdx.x;
    float4 f = reinterpret_cast<const float4*>(Wv)[i];
    __nv_bfloat162* dst = reinterpret_cast<__nv_bfloat162*>(g_wv_bf) + 2*(size_t)i;
    dst[0] = __floats2bfloat162_rn(f.x, f.y);
    dst[1] = __floats2bfloat162_rn(f.z, f.w);
}

// ---------------- kernel 2b: value fp32 -> bf16 (16B stores) ----------------
__global__ void val_convert_kernel(const float* __restrict__ value){
    size_t i = (size_t)blockIdx.x*256 + threadIdx.x;
    const float4* src = reinterpret_cast<const float4*>(value) + 2*i;
    float4 f0 = src[0], f1 = src[1];
    __nv_bfloat162 h0 = __floats2bfloat162_rn(f0.x, f0.y);
    __nv_bfloat162 h1 = __floats2bfloat162_rn(f0.z, f0.w);
    __nv_bfloat162 h2 = __floats2bfloat162_rn(f1.x, f1.y);
    __nv_bfloat162 h3 = __floats2bfloat162_rn(f1.z, f1.w);
    uint4 u;
    u.x = *(uint32_t*)&h0; u.y = *(uint32_t*)&h1;
    u.z = *(uint32_t*)&h2; u.w = *(uint32_t*)&h3;
    reinterpret_cast<uint4*>(g_val_bf)[i] = u;
}

// ---------------- kernel 3: pq[b][e] = query[b]·Wq[e] + bq[e] ----------------
__global__ void pq_kernel(const float* __restrict__ query, const float* __restrict__ Wq,
                          const float* __restrict__ bq){
    int o = blockIdx.x*8 + (threadIdx.x>>5);
    int lane = threadIdx.x & 31;
    int b = o >> 10, e = o & 1023;
    const float4* q = reinterpret_cast<const float4*>(query) + (size_t)b*256;
    const float4* w = reinterpret_cast<const float4*>(Wq) + (size_t)e*256;
    float s = 0.f;
    for (int k = lane; k < 256; k += 32){
        float4 qa = q[k], wa = w[k];
        s += qa.x*wa.x + qa.y*wa.y + qa.z*wa.z + qa.w*wa.w;
    }
    #pragma unroll
    for (int o2=16;o2;o2>>=1) s += __shfl_xor_sync(0xffffffffu, s, o2);
    if (lane==0) g_pq[o] = s + bq[e];
}

// ---------------- kernel 4: mma.sync + ldmatrix fused score kernel ----------------
// Per CTA: 128 M-rows, E in 8 chunks of 128, K streamed in 16 chunks of 64,
// 2-stage cp.async double buffer. 8 warps: warp tile 32(M) x 64(N).
#define SA 72                          // bf16 elems per smem row (144 B)
#define TILE_BYTES (128*SA*2)          // 18432 per operand tile
#define STAGE_BYTES (2*TILE_BYTES)     // A + B = 36864
#define OFF_PQ  (2*STAGE_BYTES)        // 73728
#define PQ_STRIDE 132
#define OFF_SV  (OFF_PQ + 32*PQ_STRIDE*4)  // 90624
#define OFF_RED (OFF_SV + 128*4)           // 91136
#define SMEM_TOTAL (OFF_RED + 2*128*4)     // 92160

__global__ void __launch_bounds__(256,2) score_mma_kernel(){
    extern __shared__ char smem[];
    const uint32_t sb = smem_u32(smem);
    const int tid = threadIdx.x, lane = tid & 31, warp = tid >> 5;
    const int m0 = blockIdx.x * 128;
    const int wm = (warp & 3) * 32;      // M slice
    const int wn = (warp >> 2) * 64;     // N half
    const int g  = lane >> 2, t2 = (lane & 3) * 2;

    float* sPQ  = (float*)(smem + OFF_PQ);
    float* sSV  = (float*)(smem + OFF_SV);
    float* sRed = (float*)(smem + OFF_RED);

    // per-lane ldmatrix offsets (in bf16 elems, within a tile)
    const uint32_t lrow = ((lane >> 3) & 1) * 8 + (lane & 7);
    const uint32_t lcol = (lane >> 4) * 8;
    uint32_t aoff[2], boff[4];
    #pragma unroll
    for (int m2 = 0; m2 < 2; m2++) aoff[m2] = (wm + m2*16 + lrow)*SA + lcol;
    #pragma unroll
    for (int nb = 0; nb < 4; nb++) boff[nb] = (wn + nb*16 + lrow)*SA + lcol;

    // cp.async indices: 1024 16B-chunks per tile / 256 threads = 4 each
    const int cr = tid >> 3, cc = tid & 7;   // +32 rows per iteration

    const __nv_bfloat16* Abase = g_val_bf + (size_t)m0 * D_DIM;

    float rs[2][2] = {{0.f,0.f},{0.f,0.f}};

    for (int nc = 0; nc < 8; nc++){
        __syncthreads();   // prev epilogue done: sPQ/sSV reusable
        #pragma unroll 4
        for (int t = 0; t < 16; t++){
            int idx = tid + t*256;          // 4096 = 32*128
            int b = idx >> 7, e = idx & 127;
            sPQ[b*PQ_STRIDE + e] = g_pq[b*E_DIM + nc*128 + e];
        }
        if (tid < 128) sSV[tid] = g_scale_v[nc*128 + tid];
        // (first read of sPQ happens after many __syncthreads below)

        float acc[2][8][4];
        #pragma unroll
        for (int i=0;i<2;i++)
            #pragma unroll
            for (int j=0;j<8;j++)
                #pragma unroll
                for (int k=0;k<4;k++) acc[i][j][k]=0.f;

        const __nv_bfloat16* Bbase = g_wv_bf + (size_t)(nc*128) * D_DIM;

        // prologue: stage 0 <- kc 0
        {
            const __nv_bfloat16* As = Abase;
            const __nv_bfloat16* Bs = Bbase;
            uint32_t dA = sb, dB = sb + TILE_BYTES;
            #pragma unroll
            for (int t = 0; t < 4; t++){
                int r = cr + t*32;
                uint32_t o = (uint32_t)(r*SA + cc*8)*2;
                cp_async16(dA + o, As + (size_t)r*D_DIM + cc*8);
                cp_async16(dB + o, Bs + (size_t)r*D_DIM + cc*8);
            }
            asm volatile("cp.async.commit_group;\n");
        }

        for (int kc = 0; kc < 16; kc++){
            if (kc < 15){
                const __nv_bfloat16* As = Abase + (kc+1)*64;
                const __nv_bfloat16* Bs = Bbase + (kc+1)*64;
                uint32_t dA = sb + ((kc+1)&1)*STAGE_BYTES, dB = dA + TILE_BYTES;
                #pragma unroll
                for (int t = 0; t < 4; t++){
                    int r = cr + t*32;
                    uint32_t o = (uint32_t)(r*SA + cc*8)*2;
                    cp_async16(dA + o, As + (size_t)r*D_DIM + cc*8);
                    cp_async16(dB + o, Bs + (size_t)r*D_DIM + cc*8);
                }
                asm volatile("cp.async.commit_group;\n");
                asm volatile("cp.async.wait_group 1;\n");
            } else {
                asm volatile("cp.async.wait_group 0;\n");
            }
            __syncthreads();

            const uint32_t stA = sb + (kc&1)*STAGE_BYTES;
            const uint32_t stB = stA + TILE_BYTES;
            #pragma unroll
            for (int ks = 0; ks < 4; ks++){
                const uint32_t kk = ks*16;
                uint32_t a[2][4], bq[4][4];
                ldsm_x4(a[0], stA + (aoff[0] + kk)*2);
                ldsm_x4(a[1], stA + (aoff[1] + kk)*2);
                #pragma unroll
                for (int nb = 0; nb < 4; nb++)
                    ldsm_x4(bq[nb], stB + (boff[nb] + kk)*2);
                #pragma unroll
                for (int m2 = 0; m2 < 2; m2++){
                    #pragma unroll
                    for (int nb = 0; nb < 4; nb++){
                        asm volatile(
                            "mma.sync.aligned.m16n8k16.row.col.f32.bf16.bf16.f32 "
                            "{%0,%1,%2,%3}, {%4,%5,%6,%7}, {%8,%9}, {%0,%1,%2,%3};\n"
                            : "+f"(acc[m2][2*nb][0]), "+f"(acc[m2][2*nb][1]),
                              "+f"(acc[m2][2*nb][2]), "+f"(acc[m2][2*nb][3])
                            : "r"(a[m2][0]), "r"(a[m2][1]), "r"(a[m2][2]), "r"(a[m2][3]),
                              "r"(bq[nb][0]), "r"(bq[nb][2]));
                        asm volatile(
                            "mma.sync.aligned.m16n8k16.row.col.f32.bf16.bf16.f32 "
                            "{%0,%1,%2,%3}, {%4,%5,%6,%7}, {%8,%9}, {%0,%1,%2,%3};\n"
                            : "+f"(acc[m2][2*nb+1][0]), "+f"(acc[m2][2*nb+1][1]),
                              "+f"(acc[m2][2*nb+1][2]), "+f"(acc[m2][2*nb+1][3])
                            : "r"(a[m2][0]), "r"(a[m2][1]), "r"(a[m2][2]), "r"(a[m2][3]),
                              "r"(bq[nb][1]), "r"(bq[nb][3]));
                    }
                }
            }
            __syncthreads();
        }

        // epilogue: rs += tanh(acc + pq) * scale_v  (sPQ valid: many barriers since store)
        #pragma unroll
        for (int m2 = 0; m2 < 2; m2++){
            #pragma unroll
            for (int o = 0; o < 2; o++){
                int b = (wm + m2*16 + g + o*8) & 31;
                const float* prow = sPQ + b*PQ_STRIDE;
                float acc_s = 0.f;
                #pragma unroll
                for (int nn = 0; nn < 8; nn++){
                    int c = wn + nn*8 + t2;
                    acc_s += fast_tanh(acc[m2][nn][2*o  ] + prow[c  ]) * sSV[c  ]
                           + fast_tanh(acc[m2][nn][2*o+1] + prow[c+1]) * sSV[c+1];
                }
                rs[m2][o] += acc_s;
            }
        }
    }

    // reduce over lane quads, then across the 2 N-warps
    #pragma unroll
    for (int m2 = 0; m2 < 2; m2++)
        #pragma unroll
        for (int o = 0; o < 2; o++){
            rs[m2][o] += __shfl_xor_sync(0xffffffffu, rs[m2][o], 1);
            rs[m2][o] += __shfl_xor_sync(0xffffffffu, rs[m2][o], 2);
        }
    if ((lane & 3) == 0){
        #pragma unroll
        for (int m2 = 0; m2 < 2; m2++)
            #pragma unroll
            for (int o = 0; o < 2; o++)
                sRed[(warp>>2)*128 + wm + m2*16 + o*8 + g] = rs[m2][o];
    }
    __syncthreads();
    if (tid < 128) g_scores[m0 + tid] = sRed[tid] + sRed[128 + tid];
}

// ---------------- kernel 5: softmax over s per b ----------------
__global__ void softmax_kernel(const unsigned char* __restrict__ mask,
                               float* __restrict__ out1, float* __restrict__ out2){
    __shared__ float red[32];
    __shared__ float bval;
    int b = blockIdx.x, s = threadIdx.x;
    int idx = s*B_DIM + b;
    float x = g_scores[idx];
    if (mask[idx]) x = -1e30f;

    float m = x;
    #pragma unroll
    for (int o=16;o;o>>=1) m = fmaxf(m, __shfl_xor_sync(0xffffffffu, m, o));
    if ((s&31)==0) red[s>>5] = m;
    __syncthreads();
    if (s < 32){
        float z = red[s];
        #pragma unroll
        for (int o=16;o;o>>=1) z = fmaxf(z, __shfl_xor_sync(0xffffffffu, z, o));
        if (s==0) bval = z;
    }
    __syncthreads();
    float e = __expf(x - bval);
    float t = e;
    #pragma unroll
    for (int o=16;o;o>>=1) t += __shfl_xor_sync(0xffffffffu, t, o);
    if ((s&31)==0) red[s>>5] = t;
    __syncthreads();
    if (s < 32){
        float z = red[s];
        #pragma unroll
        for (int o=16;o;o>>=1) z += __shfl_xor_sync(0xffffffffu, z, o);
        if (s==0) bval = z;
    }
    __syncthreads();
    float a = e / bval;
    g_scores[idx] = a;
    if (out1) out1[idx] = a;
    if (out2) out2[idx] = a;
}

// ---------------- kernel 6: context[b][d] = sum_s attn[s][b]*value[s][b][d] ----------------
__global__ void context_kernel(const float* __restrict__ value, float* __restrict__ ctx){
    int b = blockIdx.y;
    int d = blockIdx.x*256 + threadIdx.x;
    const float* vp = value + (size_t)b*D_DIM + d;
    float acc = 0.f;
    for (int s = 0; s < S_DIM; s += 8){
        float a[8], vv[8];
        #pragma unroll
        for (int i=0;i<8;i++){
            a[i]  = g_scores[(s+i)*B_DIM + b];
            vv[i] = vp[(size_t)(s+i)*B_DIM*D_DIM];
        }
        #pragma unroll
        for (int i=0;i<8;i++) acc += a[i]*vv[i];
    }
    ctx[(size_t)b*D_DIM + d] = acc;
}

// ---------------- launch ----------------
extern "C" void kernel_launch(void* const* d_in, const int* in_sizes, int n_in,
                              void* d_out, int out_size){
    const float* query = (const float*)d_in[0];
    const float* value = (const float*)d_in[1];
    const unsigned char* mask = (const unsigned char*)d_in[2];
    const float* Wq = (const float*)d_in[3];
    const float* bq = (const float*)d_in[4];
    const float* Wv = (const float*)d_in[5];
    const float* v  = (const float*)d_in[6];
    const float* g  = (const float*)d_in[7];
    float* out = (float*)d_out;
    (void)in_sizes; (void)n_in;

    cudaFuncSetAttribute(score_mma_kernel, cudaFuncAttributeMaxDynamicSharedMemorySize, SMEM_TOTAL);

    scale_v_kernel<<<1, 1024>>>(v, g);
    wv_convert_kernel<<<1024, 256>>>(Wv);
    val_convert_kernel<<<16384, 256>>>(value);
    pq_kernel<<<4096, 256>>>(query, Wq, bq);
    score_mma_kernel<<<M_TOTAL/128, 256, SMEM_TOTAL>>>();

    float* attn1 = (out_size >= 65536) ? out + 32768 : nullptr;
    float* attn2 = (out_size >= 98304) ? out + 65536 : nullptr;
    softmax_kernel<<<32, 1024>>>(mask, attn1, attn2);
    context_kernel<<<dim3(4,32), 256>>>(value, out);
}

// round 4
// speedup vs baseline: 1.6403x; 1.1136x over previous
#include <cuda_runtime.h>
#include <cuda_bf16.h>
#include <cstdint>

#define S_DIM 1024
#define B_DIM 32
#define D_DIM 1024
#define E_DIM 1024
#define M_TOTAL (S_DIM*B_DIM)

// ---------------- device scratch (static, no allocations) ----------------
__device__ __nv_bfloat16 g_wv_bf[E_DIM*D_DIM];            // Wv bf16 [E][D] k-major
__device__ __nv_bfloat16 g_val_bf[(size_t)M_TOTAL*D_DIM]; // value bf16 [M][D]
__device__ float g_pq[B_DIM*E_DIM];                       // projected query [B][E]
__device__ float g_scale_v[E_DIM];                        // g/||v|| * v
__device__ float g_scores[M_TOTAL];                       // raw scores -> attn [S][B]
__device__ float g_ctx_part[4*B_DIM*D_DIM];               // context s-split partials

__device__ __forceinline__ float fast_tanh(float x){
    float y; asm("tanh.approx.f32 %0, %1;" : "=f"(y) : "f"(x)); return y;
}
__device__ __forceinline__ uint32_t smem_u32(const void* p){
    return (uint32_t)__cvta_generic_to_shared(p);
}
__device__ __forceinline__ void cp_async16(uint32_t dst, const void* src){
    asm volatile("cp.async.cg.shared.global [%0], [%1], 16;\n" :: "r"(dst), "l"(src));
}
__device__ __forceinline__ void ldsm_x4(uint32_t* r, uint32_t addr){
    asm volatile("ldmatrix.sync.aligned.m8n8.x4.shared.b16 {%0,%1,%2,%3}, [%4];"
                 : "=r"(r[0]), "=r"(r[1]), "=r"(r[2]), "=r"(r[3]) : "r"(addr));
}

// ---------------- kernel 1: scale_v = g/||v|| * v ----------------
__global__ void scale_v_kernel(const float* __restrict__ v, const float* __restrict__ g){
    __shared__ float red[32];
    int t = threadIdx.x;
    float x = v[t];
    float s = x*x;
    #pragma unroll
    for (int o=16;o;o>>=1) s += __shfl_xor_sync(0xffffffffu, s, o);
    if ((t&31)==0) red[t>>5] = s;
    __syncthreads();
    if (t < 32){
        float z = red[t];
        #pragma unroll
        for (int o=16;o;o>>=1) z += __shfl_xor_sync(0xffffffffu, z, o);
        if (t==0) red[0] = z;
    }
    __syncthreads();
    float scale = g[0] / sqrtf(red[0]);
    g_scale_v[t] = scale * x;
}

// ---------------- kernel 2: Wv fp32 -> bf16 ----------------
__global__ void wv_convert_kernel(const float* __restrict__ Wv){
    int i = blockIdx.x*256 + threadIdx.x;
    float4 f = reinterpret_cast<const float4*>(Wv)[i];
    __nv_bfloat162* dst = reinterpret_cast<__nv_bfloat162*>(g_wv_bf) + 2*(size_t)i;
    dst[0] = __floats2bfloat162_rn(f.x, f.y);
    dst[1] = __floats2bfloat162_rn(f.z, f.w);
}

// ---------------- kernel 2b: value fp32 -> bf16 ----------------
__global__ void val_convert_kernel(const float* __restrict__ value){
    size_t i = (size_t)blockIdx.x*256 + threadIdx.x;
    const float4* src = reinterpret_cast<const float4*>(value) + 2*i;
    float4 f0 = src[0], f1 = src[1];
    __nv_bfloat162 h0 = __floats2bfloat162_rn(f0.x, f0.y);
    __nv_bfloat162 h1 = __floats2bfloat162_rn(f0.z, f0.w);
    __nv_bfloat162 h2 = __floats2bfloat162_rn(f1.x, f1.y);
    __nv_bfloat162 h3 = __floats2bfloat162_rn(f1.z, f1.w);
    uint4 u;
    u.x = *(uint32_t*)&h0; u.y = *(uint32_t*)&h1;
    u.z = *(uint32_t*)&h2; u.w = *(uint32_t*)&h3;
    reinterpret_cast<uint4*>(g_val_bf)[i] = u;
}

// ---------------- kernel 3: pq, smem-tiled ----------------
// grid 128: block handles 8 e's x all 32 b. Wq read once total (4MB).
__global__ void __launch_bounds__(256) pq_kernel(const float* __restrict__ query,
                          const float* __restrict__ Wq, const float* __restrict__ bq){
    __shared__ float4 sQ4[64*35];   // [kq][b], pad 35
    __shared__ float4 sW4[8*65];    // [e][kq], pad 65
    const int tid = threadIdx.x, lane = tid & 31, warp = tid >> 5;
    const int e0 = blockIdx.x * 8;
    const float4* query4 = reinterpret_cast<const float4*>(query);
    const float4* Wq4 = reinterpret_cast<const float4*>(Wq);

    float acc = 0.f;
    for (int kc = 0; kc < 4; kc++){
        __syncthreads();
        #pragma unroll
        for (int t = 0; t < 8; t++){
            int idx = tid + t*256;
            int b = idx >> 6, kq = idx & 63;
            sQ4[kq*35 + b] = query4[b*256 + kc*64 + kq];
        }
        #pragma unroll
        for (int t = 0; t < 2; t++){
            int idx = tid + t*256;
            int e = idx >> 6, kq = idx & 63;
            sW4[e*65 + kq] = Wq4[(size_t)(e0+e)*256 + kc*64 + kq];
        }
        __syncthreads();
        #pragma unroll 4
        for (int kq = 0; kq < 64; kq++){
            float4 w4 = sW4[warp*65 + kq];
            float4 q4 = sQ4[kq*35 + lane];
            acc += w4.x*q4.x + w4.y*q4.y + w4.z*q4.z + w4.w*q4.w;
        }
    }
    g_pq[lane*E_DIM + e0 + warp] = acc + bq[e0 + warp];
}

// ---------------- kernel 4: mma.sync score kernel, 3-stage 1-barrier pipeline ----
// Per CTA: 128 M-rows, E in 8 chunks of 128 (nc), K in 64-wide chunks (gk global
// index 0..127), 3-stage cp.async ring, SW128 swizzle, pq/sv read from L2 in epilogue.
#define KSTAGES 3
#define STAGE_BYTES 32768              // A 16K + B 16K, 128 rows x 128B each
#define OFF_RED (KSTAGES*STAGE_BYTES)  // 98304
#define SMEM_TOTAL (OFF_RED + 2*128*4) // 99328

__device__ __forceinline__ void score_load_stage(uint32_t sb, int m0, int cr, int cc,
                                                 int stage, int gk){
    const int i = gk & 15, nc = gk >> 4;
    const __nv_bfloat16* Abase = g_val_bf + (size_t)m0*D_DIM + i*64;
    const __nv_bfloat16* Bbase = g_wv_bf + (size_t)(nc*128)*D_DIM + i*64;
    uint32_t dA = sb + stage*STAGE_BYTES, dB = dA + 16384;
    #pragma unroll
    for (int t = 0; t < 4; t++){
        int r = cr + t*32;
        uint32_t off = (uint32_t)(r*128 + cc*16);
        off ^= (off>>3)&0x70;
        cp_async16(dA + off, Abase + (size_t)r*D_DIM + cc*8);
        cp_async16(dB + off, Bbase + (size_t)r*D_DIM + cc*8);
    }
    asm volatile("cp.async.commit_group;\n");
}

__global__ void __launch_bounds__(256,2) score_mma_kernel(){
    extern __shared__ char smem[];
    const uint32_t sb = smem_u32(smem);
    const int tid = threadIdx.x, lane = tid & 31, warp = tid >> 5;
    const int m0 = blockIdx.x * 128;
    const int wm = (warp & 3) * 32;      // M slice
    const int wn = (warp >> 2) * 64;     // N half
    const int g  = lane >> 2, t2 = (lane & 3) * 2;
    float* sRed = (float*)(smem + OFF_RED);

    // ldmatrix per-lane geometry
    const uint32_t lrow = ((lane >> 3) & 1) * 8 + (lane & 7);
    const uint32_t hi = lane >> 4;       // 0/1: high 8 columns
    const uint32_t xsw = lrow & 7;       // swizzle xor (row within 8-row atom)
    // row byte offsets (swizzle affects only the column segment)
    uint32_t arow[2], brow[4];
    #pragma unroll
    for (int m2 = 0; m2 < 2; m2++) arow[m2] = (wm + m2*16 + lrow)*128;
    #pragma unroll
    for (int nb = 0; nb < 4; nb++) brow[nb] = (wn + nb*16 + lrow)*128;
    uint32_t csw[4];
    #pragma unroll
    for (int ks = 0; ks < 4; ks++) csw[ks] = (((uint32_t)(ks*2) + hi) ^ xsw) << 4;

    // cp.async mapping: 256 threads cover 32 rows x 8 segs per pass
    const int cr = tid >> 3, cc = tid & 7;

    float rs[2][2] = {{0.f,0.f},{0.f,0.f}};

    // prologue: stages 0,1 <- gk 0,1
    score_load_stage(sb, m0, cr, cc, 0, 0);
    score_load_stage(sb, m0, cr, cc, 1, 1);

    int cur = 0;   // stage of current gk
    for (int nc = 0; nc < 8; nc++){
        float acc[2][8][4];
        #pragma unroll
        for (int i=0;i<2;i++)
            #pragma unroll
            for (int j=0;j<8;j++)
                #pragma unroll
                for (int k=0;k<4;k++) acc[i][j][k]=0.f;

        #pragma unroll 1
        for (int i = 0; i < 16; i++){
            const int gk = nc*16 + i;
            if (gk == 127) asm volatile("cp.async.wait_group 0;\n");
            else           asm volatile("cp.async.wait_group 1;\n");
            __syncthreads();
            if (gk + 2 < 128){
                int pf = cur + 2; if (pf >= 3) pf -= 3;
                score_load_stage(sb, m0, cr, cc, pf, gk + 2);
            }
            const uint32_t stA = sb + cur*STAGE_BYTES;
            const uint32_t stB = stA + 16384;
            #pragma unroll
            for (int ks = 0; ks < 4; ks++){
                uint32_t a[2][4], bq[4][4];
                ldsm_x4(a[0], stA + arow[0] + csw[ks]);
                ldsm_x4(a[1], stA + arow[1] + csw[ks]);
                #pragma unroll
                for (int nb = 0; nb < 4; nb++)
                    ldsm_x4(bq[nb], stB + brow[nb] + csw[ks]);
                #pragma unroll
                for (int m2 = 0; m2 < 2; m2++){
                    #pragma unroll
                    for (int nb = 0; nb < 4; nb++){
                        asm volatile(
                            "mma.sync.aligned.m16n8k16.row.col.f32.bf16.bf16.f32 "
                            "{%0,%1,%2,%3}, {%4,%5,%6,%7}, {%8,%9}, {%0,%1,%2,%3};\n"
                            : "+f"(acc[m2][2*nb][0]), "+f"(acc[m2][2*nb][1]),
                              "+f"(acc[m2][2*nb][2]), "+f"(acc[m2][2*nb][3])
                            : "r"(a[m2][0]), "r"(a[m2][1]), "r"(a[m2][2]), "r"(a[m2][3]),
                              "r"(bq[nb][0]), "r"(bq[nb][2]));
                        asm volatile(
                            "mma.sync.aligned.m16n8k16.row.col.f32.bf16.bf16.f32 "
                            "{%0,%1,%2,%3}, {%4,%5,%6,%7}, {%8,%9}, {%0,%1,%2,%3};\n"
                            : "+f"(acc[m2][2*nb+1][0]), "+f"(acc[m2][2*nb+1][1]),
                              "+f"(acc[m2][2*nb+1][2]), "+f"(acc[m2][2*nb+1][3])
                            : "r"(a[m2][0]), "r"(a[m2][1]), "r"(a[m2][2]), "r"(a[m2][3]),
                              "r"(bq[nb][1]), "r"(bq[nb][3]));
                    }
                }
            }
            cur++; if (cur == 3) cur = 0;
        }

        // epilogue: rs += tanh(acc + pq) * scale_v ; pq/sv straight from L2.
        // No staged-smem access here -> next gk's prefetch (already issued) overlaps.
        const float* svbase = g_scale_v + nc*128;
        float sv[16];
        #pragma unroll
        for (int nn = 0; nn < 8; nn++){
            sv[2*nn  ] = svbase[wn + nn*8 + t2];
            sv[2*nn+1] = svbase[wn + nn*8 + t2 + 1];
        }
        #pragma unroll
        for (int m2 = 0; m2 < 2; m2++){
            #pragma unroll
            for (int o = 0; o < 2; o++){
                int b = (wm + m2*16 + g + o*8) & 31;
                const float* prow = g_pq + (size_t)b*E_DIM + nc*128;
                float acc_s = 0.f;
                #pragma unroll
                for (int nn = 0; nn < 8; nn++){
                    int c = wn + nn*8 + t2;
                    acc_s += fast_tanh(acc[m2][nn][2*o  ] + prow[c  ]) * sv[2*nn  ]
                           + fast_tanh(acc[m2][nn][2*o+1] + prow[c+1]) * sv[2*nn+1];
                }
                rs[m2][o] += acc_s;
            }
        }
    }

    // reduce over lane quads, then across the 2 N-warps
    #pragma unroll
    for (int m2 = 0; m2 < 2; m2++)
        #pragma unroll
        for (int o = 0; o < 2; o++){
            rs[m2][o] += __shfl_xor_sync(0xffffffffu, rs[m2][o], 1);
            rs[m2][o] += __shfl_xor_sync(0xffffffffu, rs[m2][o], 2);
        }
    __syncthreads();
    if ((lane & 3) == 0){
        #pragma unroll
        for (int m2 = 0; m2 < 2; m2++)
            #pragma unroll
            for (int o = 0; o < 2; o++)
                sRed[(warp>>2)*128 + wm + m2*16 + o*8 + g] = rs[m2][o];
    }
    __syncthreads();
    if (tid < 128) g_scores[m0 + tid] = sRed[tid] + sRed[128 + tid];
}

// ---------------- kernel 5: softmax over s per b ----------------
__global__ void softmax_kernel(const unsigned char* __restrict__ mask,
                               float* __restrict__ out1, float* __restrict__ out2){
    __shared__ float red[32];
    __shared__ float bval;
    int b = blockIdx.x, s = threadIdx.x;
    int idx = s*B_DIM + b;
    float x = g_scores[idx];
    if (mask[idx]) x = -1e30f;

    float m = x;
    #pragma unroll
    for (int o=16;o;o>>=1) m = fmaxf(m, __shfl_xor_sync(0xffffffffu, m, o));
    if ((s&31)==0) red[s>>5] = m;
    __syncthreads();
    if (s < 32){
        float z = red[s];
        #pragma unroll
        for (int o=16;o;o>>=1) z = fmaxf(z, __shfl_xor_sync(0xffffffffu, z, o));
        if (s==0) bval = z;
    }
    __syncthreads();
    float e = __expf(x - bval);
    float t = e;
    #pragma unroll
    for (int o=16;o;o>>=1) t += __shfl_xor_sync(0xffffffffu, t, o);
    if ((s&31)==0) red[s>>5] = t;
    __syncthreads();
    if (s < 32){
        float z = red[s];
        #pragma unroll
        for (int o=16;o;o>>=1) z += __shfl_xor_sync(0xffffffffu, z, o);
        if (s==0) bval = z;
    }
    __syncthreads();
    float a = e / bval;
    g_scores[idx] = a;
    if (out1) out1[idx] = a;
    if (out2) out2[idx] = a;
}

// ---------------- kernel 6: context partials (s split 4 ways, deterministic) ----
__global__ void context_part_kernel(const float* __restrict__ value){
    int b = blockIdx.x, sc = blockIdx.y;
    int d4 = threadIdx.x;                   // float4 index over d (256 covers 1024)
    const float4* v4 = reinterpret_cast<const float4*>(value);
    float4 acc = {0.f,0.f,0.f,0.f};
    int s0 = sc * 256;
    for (int s = s0; s < s0 + 256; s += 8){
        #pragma unroll
        for (int i = 0; i < 8; i++){
            float a = g_scores[(s+i)*B_DIM + b];
            float4 vv = v4[(size_t)((s+i)*B_DIM + b)*256 + d4];
            acc.x += a*vv.x; acc.y += a*vv.y; acc.z += a*vv.z; acc.w += a*vv.w;
        }
    }
    reinterpret_cast<float4*>(g_ctx_part)[(size_t)(sc*B_DIM + b)*256 + d4] = acc;
}

__global__ void context_reduce_kernel(float* __restrict__ ctx){
    int b = blockIdx.x, d4 = threadIdx.x;
    const float4* p = reinterpret_cast<const float4*>(g_ctx_part);
    float4 a0 = p[(size_t)(0*B_DIM + b)*256 + d4];
    float4 a1 = p[(size_t)(1*B_DIM + b)*256 + d4];
    float4 a2 = p[(size_t)(2*B_DIM + b)*256 + d4];
    float4 a3 = p[(size_t)(3*B_DIM + b)*256 + d4];
    float4 o;
    o.x = (a0.x+a1.x)+(a2.x+a3.x);
    o.y = (a0.y+a1.y)+(a2.y+a3.y);
    o.z = (a0.z+a1.z)+(a2.z+a3.z);
    o.w = (a0.w+a1.w)+(a2.w+a3.w);
    reinterpret_cast<float4*>(ctx)[(size_t)b*256 + d4] = o;
}

// ---------------- launch ----------------
extern "C" void kernel_launch(void* const* d_in, const int* in_sizes, int n_in,
                              void* d_out, int out_size){
    const float* query = (const float*)d_in[0];
    const float* value = (const float*)d_in[1];
    const unsigned char* mask = (const unsigned char*)d_in[2];
    const float* Wq = (const float*)d_in[3];
    const float* bq = (const float*)d_in[4];
    const float* Wv = (const float*)d_in[5];
    const float* v  = (const float*)d_in[6];
    const float* g  = (const float*)d_in[7];
    float* out = (float*)d_out;
    (void)in_sizes; (void)n_in;

    cudaFuncSetAttribute(score_mma_kernel, cudaFuncAttributeMaxDynamicSharedMemorySize, SMEM_TOTAL);

    scale_v_kernel<<<1, 1024>>>(v, g);
    wv_convert_kernel<<<1024, 256>>>(Wv);
    val_convert_kernel<<<16384, 256>>>(value);
    pq_kernel<<<128, 256>>>(query, Wq, bq);
    score_mma_kernel<<<M_TOTAL/128, 256, SMEM_TOTAL>>>();

    float* attn1 = (out_size >= 65536) ? out + 32768 : nullptr;
    float* attn2 = (out_size >= 98304) ? out + 65536 : nullptr;
    softmax_kernel<<<32, 1024>>>(mask, attn1, attn2);
    context_part_kernel<<<dim3(32,4), 256>>>(value);
    context_reduce_kernel<<<32, 256>>>(out);
}

// round 5
// speedup vs baseline: 1.6612x; 1.0127x over previous
#include <cuda_runtime.h>
#include <cuda_bf16.h>
#include <cstdint>

#define S_DIM 1024
#define B_DIM 32
#define D_DIM 1024
#define E_DIM 1024
#define M_TOTAL (S_DIM*B_DIM)

// ---------------- device scratch (static, no allocations) ----------------
__device__ __nv_bfloat16 g_wv_bf[E_DIM*D_DIM];            // Wv bf16 [E][D] k-major
__device__ __nv_bfloat16 g_val_bf[(size_t)M_TOTAL*D_DIM]; // value bf16 [M][D]
__device__ float g_pq[B_DIM*E_DIM];                       // projected query [B][E]
__device__ float g_pq_part[8*B_DIM*E_DIM];                // pq split-k partials
__device__ float g_scale_v[E_DIM];                        // g/||v|| * v
__device__ float g_scores[M_TOTAL];                       // raw scores -> attn [S][B]
__device__ float g_ctx_part[4*B_DIM*D_DIM];               // context s-split partials

__device__ __forceinline__ float fast_tanh(float x){
    float y; asm("tanh.approx.f32 %0, %1;" : "=f"(y) : "f"(x)); return y;
}
__device__ __forceinline__ uint32_t smem_u32(const void* p){
    return (uint32_t)__cvta_generic_to_shared(p);
}
__device__ __forceinline__ void cp_async16(uint32_t dst, const void* src){
    asm volatile("cp.async.cg.shared.global [%0], [%1], 16;\n" :: "r"(dst), "l"(src));
}
__device__ __forceinline__ void ldsm_x4(uint32_t* r, uint32_t addr){
    asm volatile("ldmatrix.sync.aligned.m8n8.x4.shared.b16 {%0,%1,%2,%3}, [%4];"
                 : "=r"(r[0]), "=r"(r[1]), "=r"(r[2]), "=r"(r[3]) : "r"(addr));
}

// ---------------- kernel 1: scale_v = g/||v|| * v ----------------
__global__ void scale_v_kernel(const float* __restrict__ v, const float* __restrict__ g){
    __shared__ float red[32];
    int t = threadIdx.x;
    float x = v[t];
    float s = x*x;
    #pragma unroll
    for (int o=16;o;o>>=1) s += __shfl_xor_sync(0xffffffffu, s, o);
    if ((t&31)==0) red[t>>5] = s;
    __syncthreads();
    if (t < 32){
        float z = red[t];
        #pragma unroll
        for (int o=16;o;o>>=1) z += __shfl_xor_sync(0xffffffffu, z, o);
        if (t==0) red[0] = z;
    }
    __syncthreads();
    float scale = g[0] / sqrtf(red[0]);
    g_scale_v[t] = scale * x;
}

// ---------------- kernel 2: Wv fp32 -> bf16 ----------------
__global__ void wv_convert_kernel(const float* __restrict__ Wv){
    int i = blockIdx.x*256 + threadIdx.x;
    float4 f = reinterpret_cast<const float4*>(Wv)[i];
    __nv_bfloat162* dst = reinterpret_cast<__nv_bfloat162*>(g_wv_bf) + 2*(size_t)i;
    dst[0] = __floats2bfloat162_rn(f.x, f.y);
    dst[1] = __floats2bfloat162_rn(f.z, f.w);
}

// ---------------- kernel 2b: value fp32 -> bf16 ----------------
__global__ void val_convert_kernel(const float* __restrict__ value){
    size_t i = (size_t)blockIdx.x*256 + threadIdx.x;
    const float4* src = reinterpret_cast<const float4*>(value) + 2*i;
    float4 f0 = src[0], f1 = src[1];
    __nv_bfloat162 h0 = __floats2bfloat162_rn(f0.x, f0.y);
    __nv_bfloat162 h1 = __floats2bfloat162_rn(f0.z, f0.w);
    __nv_bfloat162 h2 = __floats2bfloat162_rn(f1.x, f1.y);
    __nv_bfloat162 h3 = __floats2bfloat162_rn(f1.z, f1.w);
    uint4 u;
    u.x = *(uint32_t*)&h0; u.y = *(uint32_t*)&h1;
    u.z = *(uint32_t*)&h2; u.w = *(uint32_t*)&h3;
    reinterpret_cast<uint4*>(g_val_bf)[i] = u;
}

// ---------------- kernel 3: pq split-k ----------------
// grid (128, 8): block = 8 e x 32 b over a 128-wide k chunk.
__global__ void __launch_bounds__(256) pq_part_kernel(const float* __restrict__ query,
                                                      const float* __restrict__ Wq){
    __shared__ float sQ[128*33 + 1];   // [k][b] transposed, stride 33
    __shared__ float sW[8*132];        // [e][k] stride 132
    const int tid = threadIdx.x;
    const int eb = blockIdx.x, kb = blockIdx.y;
    #pragma unroll
    for (int t = 0; t < 16; t++){
        int idx = tid + t*256;
        int b = idx >> 7, k = idx & 127;
        sQ[k*33 + b] = query[b*1024 + kb*128 + k];
    }
    #pragma unroll
    for (int t = 0; t < 4; t++){
        int idx = tid + t*256;
        int e = idx >> 7, k = idx & 127;
        sW[e*132 + k] = Wq[(size_t)(eb*8+e)*1024 + kb*128 + k];
    }
    __syncthreads();
    const int b = tid & 31, e = tid >> 5;
    float acc = 0.f;
    #pragma unroll 8
    for (int k = 0; k < 128; k++)
        acc += sW[e*132 + k] * sQ[k*33 + b];
    g_pq_part[((size_t)kb*32 + b)*1024 + eb*8 + e] = acc;
}

__global__ void pq_reduce_kernel(const float* __restrict__ bq){
    int idx = blockIdx.x*256 + threadIdx.x;   // 32768
    int e = idx & 1023;
    float s = bq[e];
    #pragma unroll
    for (int kb = 0; kb < 8; kb++) s += g_pq_part[(size_t)kb*32768 + idx];
    g_pq[idx] = s;
}

// ---------------- kernel 4: mma.sync score kernel ----------------
// BM=256, BN=128, 8 warps, warp tile 64x64. E in 8 chunks of 128 (nc),
// K in 64-wide chunks (gk 0..127), 3-stage cp.async ring, SW128 swizzle.
#define KSTAGES 3
#define STAGE_BYTES 49152              // A 32K (256 rows x 128B) + B 16K (128 rows)
#define OFF_RED (KSTAGES*STAGE_BYTES)  // 147456
#define SMEM_TOTAL (OFF_RED + 2*256*4) // 149504

__device__ __forceinline__ void score_load_stage(uint32_t sb, int m0, int cr, int cc,
                                                 int stage, int gk){
    const int i = gk & 15, nc = gk >> 4;
    const __nv_bfloat16* Abase = g_val_bf + (size_t)m0*D_DIM + i*64;
    const __nv_bfloat16* Bbase = g_wv_bf + (size_t)(nc*128)*D_DIM + i*64;
    uint32_t dA = sb + stage*STAGE_BYTES;
    uint32_t dB = dA + 32768;
    #pragma unroll
    for (int t = 0; t < 8; t++){                 // A: 256 rows
        int r = cr + t*32;
        uint32_t off = (uint32_t)(r*128 + cc*16); off ^= (off>>3)&0x70;
        cp_async16(dA + off, Abase + (size_t)r*D_DIM + cc*8);
    }
    #pragma unroll
    for (int t = 0; t < 4; t++){                 // B: 128 rows
        int r = cr + t*32;
        uint32_t off = (uint32_t)(r*128 + cc*16); off ^= (off>>3)&0x70;
        cp_async16(dB + off, Bbase + (size_t)r*D_DIM + cc*8);
    }
    asm volatile("cp.async.commit_group;\n");
}

__global__ void __launch_bounds__(256,1) score_mma_kernel(){
    extern __shared__ char smem[];
    const uint32_t sb = smem_u32(smem);
    const int tid = threadIdx.x, lane = tid & 31, warp = tid >> 5;
    const int m0 = blockIdx.x * 256;
    const int wm = (warp & 3) * 64;      // M slice (64 rows)
    const int wn = (warp >> 2) * 64;     // N half (64 cols)
    const int g  = lane >> 2, t2 = (lane & 3) * 2;
    float* sRed = (float*)(smem + OFF_RED);

    // ldmatrix per-lane geometry (SW128)
    const uint32_t lrow = ((lane >> 3) & 1) * 8 + (lane & 7);
    const uint32_t hi = lane >> 4;
    const uint32_t xsw = lrow & 7;
    uint32_t arow[4], brow[4];
    #pragma unroll
    for (int m2 = 0; m2 < 4; m2++) arow[m2] = (wm + m2*16 + lrow)*128;
    #pragma unroll
    for (int nb = 0; nb < 4; nb++) brow[nb] = (wn + nb*16 + lrow)*128;
    uint32_t csw[4];
    #pragma unroll
    for (int ks = 0; ks < 4; ks++) csw[ks] = (((uint32_t)(ks*2) + hi) ^ xsw) << 4;

    const int cr = tid >> 3, cc = tid & 7;

    float rs[4][2];
    #pragma unroll
    for (int i=0;i<4;i++){ rs[i][0]=0.f; rs[i][1]=0.f; }

    score_load_stage(sb, m0, cr, cc, 0, 0);
    score_load_stage(sb, m0, cr, cc, 1, 1);

    int cur = 0;
    for (int nc = 0; nc < 8; nc++){
        float acc[4][8][4];
        #pragma unroll
        for (int i=0;i<4;i++)
            #pragma unroll
            for (int j=0;j<8;j++)
                #pragma unroll
                for (int k=0;k<4;k++) acc[i][j][k]=0.f;

        #pragma unroll 1
        for (int i = 0; i < 16; i++){
            const int gk = nc*16 + i;
            if (gk == 127) asm volatile("cp.async.wait_group 0;\n");
            else           asm volatile("cp.async.wait_group 1;\n");
            __syncthreads();
            if (gk + 2 < 128){
                int pf = cur + 2; if (pf >= 3) pf -= 3;
                score_load_stage(sb, m0, cr, cc, pf, gk + 2);
            }
            const uint32_t stA = sb + cur*STAGE_BYTES;
            const uint32_t stB = stA + 32768;
            #pragma unroll
            for (int ks = 0; ks < 4; ks++){
                uint32_t a[4][4], bq[4][4];
                #pragma unroll
                for (int m2 = 0; m2 < 4; m2++)
                    ldsm_x4(a[m2], stA + arow[m2] + csw[ks]);
                #pragma unroll
                for (int nb = 0; nb < 4; nb++)
                    ldsm_x4(bq[nb], stB + brow[nb] + csw[ks]);
                #pragma unroll
                for (int m2 = 0; m2 < 4; m2++){
                    #pragma unroll
                    for (int nb = 0; nb < 4; nb++){
                        asm volatile(
                            "mma.sync.aligned.m16n8k16.row.col.f32.bf16.bf16.f32 "
                            "{%0,%1,%2,%3}, {%4,%5,%6,%7}, {%8,%9}, {%0,%1,%2,%3};\n"
                            : "+f"(acc[m2][2*nb][0]), "+f"(acc[m2][2*nb][1]),
                              "+f"(acc[m2][2*nb][2]), "+f"(acc[m2][2*nb][3])
                            : "r"(a[m2][0]), "r"(a[m2][1]), "r"(a[m2][2]), "r"(a[m2][3]),
                              "r"(bq[nb][0]), "r"(bq[nb][2]));
                        asm volatile(
                            "mma.sync.aligned.m16n8k16.row.col.f32.bf16.bf16.f32 "
                            "{%0,%1,%2,%3}, {%4,%5,%6,%7}, {%8,%9}, {%0,%1,%2,%3};\n"
                            : "+f"(acc[m2][2*nb+1][0]), "+f"(acc[m2][2*nb+1][1]),
                              "+f"(acc[m2][2*nb+1][2]), "+f"(acc[m2][2*nb+1][3])
                            : "r"(a[m2][0]), "r"(a[m2][1]), "r"(a[m2][2]), "r"(a[m2][3]),
                              "r"(bq[nb][1]), "r"(bq[nb][3]));
                    }
                }
            }
            cur++; if (cur == 3) cur = 0;
        }

        // epilogue: rs += tanh(acc + pq) * scale_v ; pq/sv from L2 (no smem touch)
        const float* svbase = g_scale_v + nc*128;
        float sv[16];
        #pragma unroll
        for (int nn = 0; nn < 8; nn++){
            sv[2*nn  ] = svbase[wn + nn*8 + t2];
            sv[2*nn+1] = svbase[wn + nn*8 + t2 + 1];
        }
        #pragma unroll
        for (int m2 = 0; m2 < 4; m2++){
            #pragma unroll
            for (int o = 0; o < 2; o++){
                int b = (wm + m2*16 + g + o*8) & 31;
                const float* prow = g_pq + (size_t)b*E_DIM + nc*128;
                float acc_s = 0.f;
                #pragma unroll
                for (int nn = 0; nn < 8; nn++){
                    int c = wn + nn*8 + t2;
                    acc_s += fast_tanh(acc[m2][nn][2*o  ] + prow[c  ]) * sv[2*nn  ]
                           + fast_tanh(acc[m2][nn][2*o+1] + prow[c+1]) * sv[2*nn+1];
                }
                rs[m2][o] += acc_s;
            }
        }
    }

    // reduce over lane quads, then across the 2 N-warps
    #pragma unroll
    for (int m2 = 0; m2 < 4; m2++)
        #pragma unroll
        for (int o = 0; o < 2; o++){
            rs[m2][o] += __shfl_xor_sync(0xffffffffu, rs[m2][o], 1);
            rs[m2][o] += __shfl_xor_sync(0xffffffffu, rs[m2][o], 2);
        }
    __syncthreads();
    if ((lane & 3) == 0){
        #pragma unroll
        for (int m2 = 0; m2 < 4; m2++)
            #pragma unroll
            for (int o = 0; o < 2; o++)
                sRed[(warp>>2)*256 + wm + m2*16 + o*8 + g] = rs[m2][o];
    }
    __syncthreads();
    g_scores[m0 + tid] = sRed[tid] + sRed[256 + tid];
}

// ---------------- kernel 5: softmax over s per b ----------------
__global__ void softmax_kernel(const unsigned char* __restrict__ mask,
                               float* __restrict__ out1, float* __restrict__ out2){
    __shared__ float red[32];
    __shared__ float bval;
    int b = blockIdx.x, s = threadIdx.x;
    int idx = s*B_DIM + b;
    float x = g_scores[idx];
    if (mask[idx]) x = -1e30f;

    float m = x;
    #pragma unroll
    for (int o=16;o;o>>=1) m = fmaxf(m, __shfl_xor_sync(0xffffffffu, m, o));
    if ((s&31)==0) red[s>>5] = m;
    __syncthreads();
    if (s < 32){
        float z = red[s];
        #pragma unroll
        for (int o=16;o;o>>=1) z = fmaxf(z, __shfl_xor_sync(0xffffffffu, z, o));
        if (s==0) bval = z;
    }
    __syncthreads();
    float e = __expf(x - bval);
    float t = e;
    #pragma unroll
    for (int o=16;o;o>>=1) t += __shfl_xor_sync(0xffffffffu, t, o);
    if ((s&31)==0) red[s>>5] = t;
    __syncthreads();
    if (s < 32){
        float z = red[s];
        #pragma unroll
        for (int o=16;o;o>>=1) z += __shfl_xor_sync(0xffffffffu, z, o);
        if (s==0) bval = z;
    }
    __syncthreads();
    float a = e / bval;
    g_scores[idx] = a;
    if (out1) out1[idx] = a;
    if (out2) out2[idx] = a;
}

// ---------------- kernel 6: context partials (s split 4 ways, deterministic) ----
__global__ void context_part_kernel(const float* __restrict__ value){
    int b = blockIdx.x, sc = blockIdx.y;
    int d4 = threadIdx.x;
    const float4* v4 = reinterpret_cast<const float4*>(value);
    float4 acc = {0.f,0.f,0.f,0.f};
    int s0 = sc * 256;
    for (int s = s0; s < s0 + 256; s += 8){
        #pragma unroll
        for (int i = 0; i < 8; i++){
            float a = g_scores[(s+i)*B_DIM + b];
            float4 vv = v4[(size_t)((s+i)*B_DIM + b)*256 + d4];
            acc.x += a*vv.x; acc.y += a*vv.y; acc.z += a*vv.z; acc.w += a*vv.w;
        }
    }
    reinterpret_cast<float4*>(g_ctx_part)[(size_t)(sc*B_DIM + b)*256 + d4] = acc;
}

__global__ void context_reduce_kernel(float* __restrict__ ctx){
    int b = blockIdx.x, d4 = threadIdx.x;
    const float4* p = reinterpret_cast<const float4*>(g_ctx_part);
    float4 a0 = p[(size_t)(0*B_DIM + b)*256 + d4];
    float4 a1 = p[(size_t)(1*B_DIM + b)*256 + d4];
    float4 a2 = p[(size_t)(2*B_DIM + b)*256 + d4];
    float4 a3 = p[(size_t)(3*B_DIM + b)*256 + d4];
    float4 o;
    o.x = (a0.x+a1.x)+(a2.x+a3.x);
    o.y = (a0.y+a1.y)+(a2.y+a3.y);
    o.z = (a0.z+a1.z)+(a2.z+a3.z);
    o.w = (a0.w+a1.w)+(a2.w+a3.w);
    reinterpret_cast<float4*>(ctx)[(size_t)b*256 + d4] = o;
}

// ---------------- launch ----------------
extern "C" void kernel_launch(void* const* d_in, const int* in_sizes, int n_in,
                              void* d_out, int out_size){
    const float* query = (const float*)d_in[0];
    const float* value = (const float*)d_in[1];
    const unsigned char* mask = (const unsigned char*)d_in[2];
    const float* Wq = (const float*)d_in[3];
    const float* bq = (const float*)d_in[4];
    const float* Wv = (const float*)d_in[5];
    const float* v  = (const float*)d_in[6];
    const float* g  = (const float*)d_in[7];
    float* out = (float*)d_out;
    (void)in_sizes; (void)n_in;

    cudaFuncSetAttribute(score_mma_kernel, cudaFuncAttributeMaxDynamicSharedMemorySize, SMEM_TOTAL);

    scale_v_kernel<<<1, 1024>>>(v, g);
    wv_convert_kernel<<<1024, 256>>>(Wv);
    val_convert_kernel<<<16384, 256>>>(value);
    pq_part_kernel<<<dim3(128,8), 256>>>(query, Wq);
    pq_reduce_kernel<<<128, 256>>>(bq);
    score_mma_kernel<<<M_TOTAL/256, 256, SMEM_TOTAL>>>();

    float* attn1 = (out_size >= 65536) ? out + 32768 : nullptr;
    float* attn2 = (out_size >= 98304) ? out + 65536 : nullptr;
    softmax_kernel<<<32, 1024>>>(mask, attn1, attn2);
    context_part_kernel<<<dim3(32,4), 256>>>(value);
    context_reduce_kernel<<<32, 256>>>(out);
}